// round 1
// baseline (speedup 1.0000x reference)
#include <cuda_runtime.h>

// ---------------- constants ----------------
#define BB 64
#define C_IN 256
#define CH 128
#define NPH 64
#define RR 16
#define SP 256          // R*R spatial
#define ED 128
#define CBQ 8
#define NL 4
#define NE 1024
#define C_OUT 256
#define FLAT_PH 16384   // NPH*R*R
#define FLAT_Z 4096     // ED*CB*NL
#define NROWS 2048      // B*CB*NL
#define OUT_ELEMS (BB*C_OUT*SP)   // 4194304

typedef unsigned long long u64;

#define DINLINE __device__ __forceinline__

DINLINE u64 pack2(float lo, float hi){ u64 r; asm("mov.b64 %0, {%1,%2};" : "=l"(r) : "f"(lo), "f"(hi)); return r; }
DINLINE void unpack2(u64 v, float &lo, float &hi){ asm("mov.b64 {%0,%1}, %2;" : "=f"(lo), "=f"(hi) : "l"(v)); }
DINLINE u64 fma2(u64 a, u64 b, u64 c){ u64 d; asm("fma.rn.f32x2 %0, %1, %2, %3;" : "=l"(d) : "l"(a), "l"(b), "l"(c)); return d; }
DINLINE float silu_f(float x){ return x / (1.f + __expf(-x)); }

// 4x4 microtile update using packed f32x2 FMAs (8 FFMA2 per k-step)
DINLINE void fma_4x4(u64 (&acc)[4][2], float4 a, float4 b){
    u64 b01 = pack2(b.x, b.y), b23 = pack2(b.z, b.w);
    u64 aa;
    aa = pack2(a.x, a.x); acc[0][0]=fma2(aa,b01,acc[0][0]); acc[0][1]=fma2(aa,b23,acc[0][1]);
    aa = pack2(a.y, a.y); acc[1][0]=fma2(aa,b01,acc[1][0]); acc[1][1]=fma2(aa,b23,acc[1][1]);
    aa = pack2(a.z, a.z); acc[2][0]=fma2(aa,b01,acc[2][0]); acc[2][1]=fma2(aa,b23,acc[2][1]);
    aa = pack2(a.w, a.w); acc[3][0]=fma2(aa,b01,acc[3][0]); acc[3][1]=fma2(aa,b23,acc[3][1]);
}

// ---------------- scratch (device globals; no allocs) ----------------
__device__ float g_hphylo[BB*FLAT_PH];   // conv_in phylo half (pre-LN)
__device__ float g_himg  [BB*FLAT_PH];   // conv_in img half (raw)
__device__ float g_hn    [BB*FLAT_PH];   // layernormed phylo
__device__ float g_stats [BB*2];         // mu, rstd per batch
__device__ float g_zp    [2*BB*FLAT_Z];  // split-K partials of mlp_in
__device__ float g_z     [BB*FLAT_Z];    // z
__device__ float g_zq    [BB*FLAT_Z];    // quantized z (codebook gather)
__device__ float g_hout  [BB*FLAT_PH];   // mlp_out output
__device__ float g_cnorm [NE];           // |codebook_e|^2
__device__ u64   g_key   [NROWS];        // packed (sortable_dist<<32)|idx
__device__ float g_losspart[NROWS];

// ---------------- conv_in: h = W @ silu(x) + b, split into phylo/img ----------------
__global__ void __launch_bounds__(256) conv_in_k(const float* __restrict__ x,
                                                 const float* __restrict__ W,
                                                 const float* __restrict__ bias)
{
    // grid: 64 b * 2 o-tiles * 4 p-tiles = 512 blocks
    int bidx = blockIdx.x;
    int b  = bidx >> 3;
    int ot = (bidx >> 2) & 1;
    int pt = bidx & 3;
    int obase = ot * 64, pbase = pt * 64;

    __shared__ float Ws[16][68];  // Ws[c][o]
    __shared__ float Xs[16][68];  // Xs[c][p] (silu applied)

    int tid = threadIdx.x;
    int tx = tid & 15, ty = tid >> 4;
    int m0 = ty * 4, j0 = tx * 4;          // m0 -> o, j0 -> p
    int lr = tid >> 2, kq = (tid & 3) * 4; // weight load mapping
    int cl = tid >> 4, pl = (tid & 15) * 4;// x load mapping

    u64 acc[4][2];
    #pragma unroll
    for (int i=0;i<4;i++){ acc[i][0]=pack2(0.f,0.f); acc[i][1]=acc[i][0]; }

    for (int ck = 0; ck < C_IN; ck += 16){
        float4 wv = *(const float4*)(W + (obase+lr)*C_IN + ck + kq);
        Ws[kq+0][lr]=wv.x; Ws[kq+1][lr]=wv.y; Ws[kq+2][lr]=wv.z; Ws[kq+3][lr]=wv.w;
        float4 xv = *(const float4*)(x + b*(C_IN*SP) + (ck+cl)*SP + pbase + pl);
        Xs[cl][pl+0]=silu_f(xv.x); Xs[cl][pl+1]=silu_f(xv.y);
        Xs[cl][pl+2]=silu_f(xv.z); Xs[cl][pl+3]=silu_f(xv.w);
        __syncthreads();
        #pragma unroll
        for (int k=0;k<16;k++){
            float4 a = *(const float4*)&Ws[k][m0];
            float4 bv = *(const float4*)&Xs[k][j0];
            fma_4x4(acc, a, bv);
        }
        __syncthreads();
    }

    #pragma unroll
    for (int i=0;i<4;i++){
        int o = obase + m0 + i;
        float bo = bias[o];
        float v0,v1,v2,v3;
        unpack2(acc[i][0], v0, v1); unpack2(acc[i][1], v2, v3);
        float4 ov; ov.x=v0+bo; ov.y=v1+bo; ov.z=v2+bo; ov.w=v3+bo;
        float* dst = (o < NPH) ? (g_hphylo + b*FLAT_PH + o*SP)
                               : (g_himg   + b*FLAT_PH + (o-NPH)*SP);
        *(float4*)(dst + pbase + j0) = ov;
    }
}

// ---------------- layernorm stats (per batch over 16384 elems) ----------------
__global__ void __launch_bounds__(256) ln_stats_k()
{
    int b = blockIdx.x;
    const float4* p = (const float4*)(g_hphylo + b*FLAT_PH);
    float s = 0.f, s2 = 0.f;
    for (int i = threadIdx.x; i < FLAT_PH/4; i += 256){
        float4 v = p[i];
        s  += v.x + v.y + v.z + v.w;
        s2 += v.x*v.x + v.y*v.y + v.z*v.z + v.w*v.w;
    }
    __shared__ float rs[256], rq[256];
    rs[threadIdx.x] = s; rq[threadIdx.x] = s2;
    __syncthreads();
    for (int off = 128; off; off >>= 1){
        if (threadIdx.x < off){ rs[threadIdx.x]+=rs[threadIdx.x+off]; rq[threadIdx.x]+=rq[threadIdx.x+off]; }
        __syncthreads();
    }
    if (threadIdx.x == 0){
        float mu = rs[0] * (1.f/FLAT_PH);
        float var = rq[0] * (1.f/FLAT_PH) - mu*mu;
        g_stats[b*2+0] = mu;
        g_stats[b*2+1] = rsqrtf(var + 1e-5f);
    }
}

__global__ void __launch_bounds__(256) ln_norm_k(const float* __restrict__ lnw,
                                                 const float* __restrict__ lnb)
{
    int b = blockIdx.x;
    int base = blockIdx.y * 1024 + threadIdx.x * 4;
    float mu = g_stats[b*2+0], rstd = g_stats[b*2+1];
    float4 v = *(const float4*)(g_hphylo + b*FLAT_PH + base);
    float4 w = *(const float4*)(lnw + base);
    float4 bb = *(const float4*)(lnb + base);
    float4 o;
    o.x = (v.x-mu)*rstd*w.x + bb.x;
    o.y = (v.y-mu)*rstd*w.y + bb.y;
    o.z = (v.z-mu)*rstd*w.z + bb.z;
    o.w = (v.w-mu)*rstd*w.w + bb.w;
    *(float4*)(g_hn + b*FLAT_PH + base) = o;
}

// ---------------- generic skinny GEMM: C[64 x N] = A[64 x K] @ W[N x K]^T ----------------
// grid.x = N/64 tiles, grid.y = K splits (kchunk each). Partial split s writes C + s*64*N.
__global__ void __launch_bounds__(256) mlp_gemm_k(const float* __restrict__ A,
                                                  const float* __restrict__ W,
                                                  float* __restrict__ C,
                                                  const float* __restrict__ bias,
                                                  int K, int N, int kchunk)
{
    __shared__ float As[16][68];   // As[k][m]
    __shared__ float Bs[16][68];   // Bs[k][j]
    int tid = threadIdx.x;
    int jbase = blockIdx.x * 64;
    int k0 = blockIdx.y * kchunk;
    float* Cout = C + (size_t)blockIdx.y * 64 * N;
    int tx = tid & 15, ty = tid >> 4;
    int m0 = ty * 4, j0 = tx * 4;
    int lr = tid >> 2, kq = (tid & 3) * 4;

    u64 acc[4][2];
    #pragma unroll
    for (int i=0;i<4;i++){ acc[i][0]=pack2(0.f,0.f); acc[i][1]=acc[i][0]; }

    const float* Wp = W + (size_t)(jbase + lr) * K;
    const float* Ap = A + (size_t)lr * K;

    for (int kt = k0; kt < k0 + kchunk; kt += 16){
        float4 av = *(const float4*)(Ap + kt + kq);
        float4 wv = *(const float4*)(Wp + kt + kq);
        As[kq+0][lr]=av.x; As[kq+1][lr]=av.y; As[kq+2][lr]=av.z; As[kq+3][lr]=av.w;
        Bs[kq+0][lr]=wv.x; Bs[kq+1][lr]=wv.y; Bs[kq+2][lr]=wv.z; Bs[kq+3][lr]=wv.w;
        __syncthreads();
        #pragma unroll
        for (int k=0;k<16;k++){
            float4 a = *(const float4*)&As[k][m0];
            float4 b = *(const float4*)&Bs[k][j0];
            fma_4x4(acc, a, b);
        }
        __syncthreads();
    }

    #pragma unroll
    for (int i=0;i<4;i++){
        float v0,v1,v2,v3;
        unpack2(acc[i][0], v0, v1); unpack2(acc[i][1], v2, v3);
        float4 o;
        if (bias){
            o.x = v0 + bias[jbase+j0+0];
            o.y = v1 + bias[jbase+j0+1];
            o.z = v2 + bias[jbase+j0+2];
            o.w = v3 + bias[jbase+j0+3];
        } else { o.x=v0; o.y=v1; o.z=v2; o.w=v3; }
        *(float4*)(Cout + (size_t)(m0+i)*N + jbase + j0) = o;
    }
}

// ---------------- combine split-K partials + bias -> z ----------------
__global__ void __launch_bounds__(256) combine_z_k(const float* __restrict__ bias)
{
    int i = blockIdx.x * 256 + threadIdx.x;      // float4 index, 65536 total
    float4 a = ((const float4*)g_zp)[i];
    float4 b = ((const float4*)g_zp)[i + BB*FLAT_Z/4];
    int j = (i * 4) & (FLAT_Z - 1);
    float4 bv = *(const float4*)(bias + j);
    float4 o;
    o.x=a.x+b.x+bv.x; o.y=a.y+b.y+bv.y; o.z=a.z+b.z+bv.z; o.w=a.w+b.w+bv.w;
    ((float4*)g_z)[i] = o;
}

// ---------------- codebook norms ----------------
__global__ void __launch_bounds__(256) cnorm_k(const float* __restrict__ cb)
{
    int e = blockIdx.x * 256 + threadIdx.x;
    const float4* r = (const float4*)(cb + e*ED);
    float s = 0.f;
    #pragma unroll 8
    for (int i = 0; i < ED/4; i++){
        float4 v = r[i];
        s += v.x*v.x + v.y*v.y + v.z*v.z + v.w*v.w;
    }
    g_cnorm[e] = s;
}

__global__ void __launch_bounds__(256) vq_init_k()
{
    int i = blockIdx.x * 256 + threadIdx.x;
    g_key[i] = ~0ULL;
    g_losspart[i] = 0.f;
}

// ---------------- VQ distance GEMM + argmin ----------------
// block computes 64 rows (2 batches) x 128 codebook entries, K=128
__global__ void __launch_bounds__(256) vq_gemm_k(const float* __restrict__ cb)
{
    int rbase = blockIdx.x * 64;
    int ebase = blockIdx.y * 128;
    int b0 = rbase >> 5;   // 2 batches per block

    __shared__ float Zs[32][68];    // Zs[k][r]
    __shared__ float Cs[32][132];   // Cs[k][e]
    __shared__ float cn[128];

    int tid = threadIdx.x;
    if (tid < 128) cn[tid] = g_cnorm[ebase + tid];
    int tx = tid & 15, ty = tid >> 4;
    int r0 = ty * 4, e0 = tx * 8;

    float acc[4][8];
    #pragma unroll
    for (int i=0;i<4;i++)
        #pragma unroll
        for (int j=0;j<8;j++) acc[i][j] = 0.f;

    for (int kc = 0; kc < ED; kc += 32){
        #pragma unroll
        for (int it = 0; it < 2; it++){
            int i = tid + it*256;          // 0..511 float4s
            int brel = i >> 8;
            int t = (i & 255) * 4;         // 0..1020, contiguous within batch row
            float4 v = *(const float4*)(g_z + (b0+brel)*FLAT_Z + kc*32 + t);
            int k = t >> 5, s = t & 31;
            *(float4*)&Zs[k][brel*32 + s] = v;
        }
        #pragma unroll
        for (int it = 0; it < 4; it++){
            int i = tid + it*256;          // 0..1023 float4s
            int el = i >> 3; int kq = (i & 7) * 4;
            float4 v = *(const float4*)(cb + (ebase+el)*ED + kc + kq);
            Cs[kq+0][el]=v.x; Cs[kq+1][el]=v.y; Cs[kq+2][el]=v.z; Cs[kq+3][el]=v.w;
        }
        __syncthreads();
        #pragma unroll 4
        for (int k = 0; k < 32; k++){
            float4 a  = *(const float4*)&Zs[k][r0];
            float4 c0 = *(const float4*)&Cs[k][e0];
            float4 c1 = *(const float4*)&Cs[k][e0+4];
            float av[4] = {a.x,a.y,a.z,a.w};
            float cv[8] = {c0.x,c0.y,c0.z,c0.w,c1.x,c1.y,c1.z,c1.w};
            #pragma unroll
            for (int i=0;i<4;i++)
                #pragma unroll
                for (int j=0;j<8;j++) acc[i][j] = fmaf(av[i], cv[j], acc[i][j]);
        }
        __syncthreads();
    }

    #pragma unroll
    for (int i=0;i<4;i++){
        float best = 3.4e38f; int be = 0;
        #pragma unroll
        for (int j=0;j<8;j++){
            float d = cn[e0+j] - 2.f*acc[i][j];
            if (d < best){ best = d; be = e0+j; }
        }
        unsigned int bits = __float_as_uint(best);
        unsigned int key32 = (bits & 0x80000000u) ? ~bits : (bits | 0x80000000u);
        u64 key = ((u64)key32 << 32) | (unsigned)(ebase + be);
        atomicMin(&g_key[rbase + r0 + i], key);
    }
}

// ---------------- gather zq + per-row loss partial ----------------
__global__ void __launch_bounds__(128) vq_gather_k(const float* __restrict__ cb)
{
    int r = blockIdx.x;
    int b = r >> 5, s = r & 31;
    int e = (int)(unsigned)(g_key[r] & 0xFFFFFFFFULL);
    int k = threadIdx.x;
    float c = cb[e*ED + k];
    float z = g_z[b*FLAT_Z + k*32 + s];
    g_zq[b*FLAT_Z + k*32 + s] = c;
    float d = c - z; d = d * d;
    #pragma unroll
    for (int off = 16; off; off >>= 1) d += __shfl_down_sync(0xffffffffu, d, off);
    __shared__ float red[4];
    if ((threadIdx.x & 31) == 0) red[threadIdx.x >> 5] = d;
    __syncthreads();
    if (threadIdx.x == 0) g_losspart[r] = red[0]+red[1]+red[2]+red[3];
}

__global__ void __launch_bounds__(256) loss_reduce_k(float* __restrict__ dst)
{
    float s = 0.f;
    for (int i = threadIdx.x; i < NROWS; i += 256) s += g_losspart[i];
    __shared__ float rs[256];
    rs[threadIdx.x] = s;
    __syncthreads();
    for (int off = 128; off; off >>= 1){
        if (threadIdx.x < off) rs[threadIdx.x] += rs[threadIdx.x+off];
        __syncthreads();
    }
    if (threadIdx.x == 0) *dst = rs[0] * (1.25f / (float)(BB*FLAT_Z));
}

// ---------------- conv_out: out = W2 @ silu(concat(hout, himg)) + b2 ----------------
__global__ void __launch_bounds__(256) conv_out_k(const float* __restrict__ W,
                                                  const float* __restrict__ bias,
                                                  float* __restrict__ out)
{
    // grid: 64 b * 4 o-tiles * 4 p-tiles = 1024 blocks
    int bidx = blockIdx.x;
    int b  = bidx >> 4;
    int ot = (bidx >> 2) & 3;
    int pt = bidx & 3;
    int obase = ot * 64, pbase = pt * 64;

    __shared__ float Ws[16][68];
    __shared__ float Xs[16][68];

    int tid = threadIdx.x;
    int tx = tid & 15, ty = tid >> 4;
    int m0 = ty * 4, j0 = tx * 4;
    int lr = tid >> 2, kq = (tid & 3) * 4;
    int cl = tid >> 4, pl = (tid & 15) * 4;

    u64 acc[4][2];
    #pragma unroll
    for (int i=0;i<4;i++){ acc[i][0]=pack2(0.f,0.f); acc[i][1]=acc[i][0]; }

    for (int ck = 0; ck < CH; ck += 16){
        float4 wv = *(const float4*)(W + (obase+lr)*CH + ck + kq);
        Ws[kq+0][lr]=wv.x; Ws[kq+1][lr]=wv.y; Ws[kq+2][lr]=wv.z; Ws[kq+3][lr]=wv.w;
        const float* src = (ck < NPH) ? (g_hout + b*FLAT_PH + ck*SP)
                                      : (g_himg + b*FLAT_PH + (ck-NPH)*SP);
        float4 xv = *(const float4*)(src + cl*SP + pbase + pl);
        Xs[cl][pl+0]=silu_f(xv.x); Xs[cl][pl+1]=silu_f(xv.y);
        Xs[cl][pl+2]=silu_f(xv.z); Xs[cl][pl+3]=silu_f(xv.w);
        __syncthreads();
        #pragma unroll
        for (int k=0;k<16;k++){
            float4 a = *(const float4*)&Ws[k][m0];
            float4 bv = *(const float4*)&Xs[k][j0];
            fma_4x4(acc, a, bv);
        }
        __syncthreads();
    }

    #pragma unroll
    for (int i=0;i<4;i++){
        int o = obase + m0 + i;
        float bo = bias[o];
        float v0,v1,v2,v3;
        unpack2(acc[i][0], v0, v1); unpack2(acc[i][1], v2, v3);
        float4 ov; ov.x=v0+bo; ov.y=v1+bo; ov.z=v2+bo; ov.w=v3+bo;
        *(float4*)(out + (size_t)b*(C_OUT*SP) + o*SP + pbase + j0) = ov;
    }
}

// ---------------- launcher ----------------
extern "C" void kernel_launch(void* const* d_in, const int* in_sizes, int n_in,
                              void* d_out, int out_size)
{
    (void)in_sizes; (void)n_in;
    const float* x   = (const float*)d_in[0];
    const float* ciw = (const float*)d_in[1];
    const float* cib = (const float*)d_in[2];
    const float* lnw = (const float*)d_in[3];
    const float* lnb = (const float*)d_in[4];
    const float* miw = (const float*)d_in[5];
    const float* mib = (const float*)d_in[6];
    const float* cbk = (const float*)d_in[7];
    const float* mow = (const float*)d_in[8];
    const float* mob = (const float*)d_in[9];
    const float* cow = (const float*)d_in[10];
    const float* cob = (const float*)d_in[11];
    float* out = (float*)d_out;

    float *hn_p, *zp_p, *zq_p, *hout_p;
    cudaGetSymbolAddress((void**)&hn_p,   g_hn);
    cudaGetSymbolAddress((void**)&zp_p,   g_zp);
    cudaGetSymbolAddress((void**)&zq_p,   g_zq);
    cudaGetSymbolAddress((void**)&hout_p, g_hout);

    conv_in_k<<<512, 256>>>(x, ciw, cib);
    ln_stats_k<<<64, 256>>>();
    ln_norm_k<<<dim3(64, 16), 256>>>(lnw, lnb);

    // mlp_in: z_partials = hn @ W_in^T   (split-K = 2 -> 128 blocks)
    mlp_gemm_k<<<dim3(FLAT_Z/64, 2), 256>>>(hn_p, miw, zp_p, nullptr,
                                            FLAT_PH, FLAT_Z, FLAT_PH/2);
    combine_z_k<<<BB*FLAT_Z/4/256, 256>>>(mib);

    cnorm_k<<<NE/256, 256>>>(cbk);
    vq_init_k<<<NROWS/256, 256>>>();
    vq_gemm_k<<<dim3(NROWS/64, NE/128), 256>>>(cbk);
    vq_gather_k<<<NROWS, 128>>>(cbk);

    // mlp_out: hout = zq @ W_out^T + b  (256 blocks)
    mlp_gemm_k<<<dim3(FLAT_PH/64, 1), 256>>>(zq_p, mow, hout_p, mob,
                                             FLAT_Z, FLAT_PH, FLAT_Z);

    conv_out_k<<<1024, 256>>>(cow, cob, out);

    if (out_size > OUT_ELEMS)
        loss_reduce_k<<<1, 256>>>(out + out_size - 1);
}